// round 16
// baseline (speedup 1.0000x reference)
#include <cuda_runtime.h>
#include <cuda_bf16.h>
#include <cstdint>

// PathRaster2d FINAL (R16 = R12 + 2-load kp fetch): 4096 blocks (128x8
// tiles, 2D grid) x 256 threads. Each thread: ONE STG.128 zero issued first
// (no input dependency), then a control-point-bbox reject (convex hull:
// every curve sample lies in the cp bbox; margin 2.5 > LINE_WIDTH covers fp
// rounding and only ever keeps extra tiles). Bbox-hit tiles run the proven
// per-lane sample + exact per-sample box prune + full 32-sample min —
// per-pixel arithmetic bit-identical to the reference (rel_err 0.0 across
// all rounds).
//
// Measured floor: ~4us launch/clock-ramp + ~2us store drain; 15 config
// variants span 6.1-7.9us ncu. This is the best-measured configuration.

#define CANVAS_H 2048
#define CANVAS_W 2048
#define TILE_W 128
#define TILE_H 8

__global__ void __launch_bounds__(256)
path_raster_kernel(const float* __restrict__ kp, float* __restrict__ out)
{
    const int tx = threadIdx.x;          // 0..31 (lane == sample index)
    const int ty = threadIdx.y;          // 0..7
    const int x0 = blockIdx.x * TILE_W;
    const int y0 = blockIdx.y * TILE_H;

    const int x = x0 + tx * 4;
    const int y = y0 + ty;
    float* base = out + (size_t)y * CANVAS_W + x;

    // ---- phase 1: one unconditional zero store, no input dependency ----
    *reinterpret_cast<float4*>(base) = make_float4(0.0f, 0.0f, 0.0f, 0.0f);

    // ---- phase 2: exact reject via control-point bbox (hull property) ----
    float4 k03 = __ldg((const float4*)kp);        // y0n x0n y1n x1n
    float2 k45 = __ldg((const float2*)(kp + 4));  // y2n x2n
    float ky0 = __fmul_rn(k03.x, 2048.0f), kx0 = __fmul_rn(k03.y, 2048.0f);
    float ky1 = __fmul_rn(k03.z, 2048.0f), kx1 = __fmul_rn(k03.w, 2048.0f);
    float ky2 = __fmul_rn(k45.x, 2048.0f), kx2 = __fmul_rn(k45.y, 2048.0f);

    float ymin = fminf(fminf(ky0, ky1), ky2) - 2.5f;
    float ymax = fmaxf(fmaxf(ky0, ky1), ky2) + 2.5f;
    float xmin = fminf(fminf(kx0, kx1), kx2) - 2.5f;
    float xmax = fmaxf(fmaxf(kx0, kx1), kx2) + 2.5f;

    if ((float)(y0 + TILE_H - 1) < ymin || (float)y0 > ymax ||
        (float)(x0 + TILE_W - 1) < xmin || (float)x0 > xmax)
        return;                           // ~99% of warps exit here

    // ---- phase 3: per-lane sample (ref-matched rounding), exact box prune ----
    // t_i = i * fl(1/31), endpoint forced to 1.0 (matches jnp.linspace)
    float t = (tx == 31) ? 1.0f : (float)tx * (1.0f / 31.0f);
    float u = __fsub_rn(1.0f, t);
    float b0 = __fmul_rn(u, u);
    float b1 = __fmul_rn(__fmul_rn(2.0f, t), u);
    float b2 = __fmul_rn(t, t);
    float py = __fadd_rn(__fadd_rn(__fmul_rn(b0, ky0), __fmul_rn(b1, ky1)),
                         __fmul_rn(b2, ky2));
    float px = __fadd_rn(__fadd_rn(__fmul_rn(b0, kx0), __fmul_rn(b1, kx1)),
                         __fmul_rn(b2, kx2));

    // Exact point-to-tile-box distance; squared threshold 4.5 (> 4.0) pads for
    // rounding — only ever KEEPS extra samples (dist(pixel,s) >= boxdist(s)).
    float bdy = fmaxf(fmaxf((float)y0 - py, py - (float)(y0 + TILE_H - 1)), 0.0f);
    float bdx = fmaxf(fmaxf((float)x0 - px, px - (float)(x0 + TILE_W - 1)), 0.0f);
    bool near = (bdy * bdy + bdx * bdx) < 4.5f;
    unsigned mask = __ballot_sync(0xffffffffu, near);

    if (mask == 0u) return;

    // ---- phase 4 (rare): full min for this thread's 4 pixels, overwrite ----
    const float maxd = sqrtf(2048.0f * 2048.0f + 2048.0f * 2048.0f);
    const float fy  = (float)y;
    const float fx0 = (float)x;
    const float fx1 = fx0 + 1.0f;
    const float fx2 = fx0 + 2.0f;
    const float fx3 = fx0 + 3.0f;
    float m0 = 3.4e38f, m1 = 3.4e38f, m2 = 3.4e38f, m3 = 3.4e38f;
    unsigned mm = mask;                  // warp-uniform loop
    while (mm) {
        int lane = __ffs(mm) - 1;
        mm &= mm - 1u;
        float syv = __shfl_sync(0xffffffffu, py, lane);
        float sxv = __shfl_sync(0xffffffffu, px, lane);
        float dy  = __fsub_rn(fy, syv);
        float dy2 = __fmul_rn(dy, dy);   // separate op, matches reference
        float d;
        d = __fsub_rn(fx0, sxv); m0 = fminf(m0, __fadd_rn(dy2, __fmul_rn(d, d)));
        d = __fsub_rn(fx1, sxv); m1 = fminf(m1, __fadd_rn(dy2, __fmul_rn(d, d)));
        d = __fsub_rn(fx2, sxv); m2 = fminf(m2, __fadd_rn(dy2, __fmul_rn(d, d)));
        d = __fsub_rn(fx3, sxv); m3 = fminf(m3, __fadd_rn(dy2, __fmul_rn(d, d)));
    }
    // sqrt BEFORE compare (boundary rounding identical to reference)
    float d0 = sqrtf(m0), d1 = sqrtf(m1), d2s = sqrtf(m2), d3 = sqrtf(m3);
    float4 v;
    v.x = (d0  < 2.0f) ? __fsub_rn(1.0f, __fdiv_rn(d0,  maxd)) : 0.0f;
    v.y = (d1  < 2.0f) ? __fsub_rn(1.0f, __fdiv_rn(d1,  maxd)) : 0.0f;
    v.z = (d2s < 2.0f) ? __fsub_rn(1.0f, __fdiv_rn(d2s, maxd)) : 0.0f;
    v.w = (d3  < 2.0f) ? __fsub_rn(1.0f, __fdiv_rn(d3,  maxd)) : 0.0f;
    *reinterpret_cast<float4*>(base) = v;
}

extern "C" void kernel_launch(void* const* d_in, const int* in_sizes, int n_in,
                              void* d_out, int out_size)
{
    const float* kp = (const float*)d_in[0];   // [3,2] normalized (y,x)
    float* out = (float*)d_out;                // [2048,2048] fp32

    dim3 block(32, 8);
    dim3 grid(CANVAS_W / TILE_W, CANVAS_H / TILE_H);  // (16, 256) = 4096 blocks
    path_raster_kernel<<<grid, block>>>(kp, out);
}

// round 17
// speedup vs baseline: 1.0036x; 1.0036x over previous
#include <cuda_runtime.h>
#include <cuda_bf16.h>
#include <cstdint>

// PathRaster2d FINAL = R12 verbatim (session-best dur_us 8.608).
// 4096 blocks (128x8 tiles, 2D grid) x 256 threads. Each thread: ONE STG.128
// zero issued first (no input dependency), then a control-point-bbox reject
// (convex hull: every curve sample lies in the cp bbox; margin 2.5 >
// LINE_WIDTH covers fp rounding and only ever keeps extra tiles). Bbox-hit
// tiles run per-lane sample + exact per-sample box prune + full 32-sample
// min — per-pixel arithmetic bit-identical to the reference (rel_err 0.0
// across all 14 passing rounds).
//
// Session findings: ~4us fixed launch/clock-ramp floor + ~2us store drain;
// no resource >30% utilized at the optimum; 16 structural variants span
// 6.1-7.9us ncu / 8.61-8.93us dur. This is the measured-best configuration.

#define CANVAS_H 2048
#define CANVAS_W 2048
#define TILE_W 128
#define TILE_H 8

__global__ void __launch_bounds__(256)
path_raster_kernel(const float* __restrict__ kp, float* __restrict__ out)
{
    const int tx = threadIdx.x;          // 0..31 (lane == sample index)
    const int ty = threadIdx.y;          // 0..7
    const int x0 = blockIdx.x * TILE_W;
    const int y0 = blockIdx.y * TILE_H;

    const int x = x0 + tx * 4;
    const int y = y0 + ty;
    float* base = out + (size_t)y * CANVAS_W + x;

    // ---- phase 1: one unconditional zero store, no input dependency ----
    *reinterpret_cast<float4*>(base) = make_float4(0.0f, 0.0f, 0.0f, 0.0f);

    // ---- phase 2: cheap exact reject via control-point bbox ----
    // (hull property: samples subset of cp bbox; margin 2.5 > 2.0 covers fp
    //  rounding and only ever keeps extra tiles)
    float2 k01 = __ldg((const float2*)kp);        // (y0n, x0n)
    float2 k23 = __ldg((const float2*)kp + 1);    // (y1n, x1n)
    float2 k45 = __ldg((const float2*)kp + 2);    // (y2n, x2n)
    float ky0 = __fmul_rn(k01.x, 2048.0f), kx0 = __fmul_rn(k01.y, 2048.0f);
    float ky1 = __fmul_rn(k23.x, 2048.0f), kx1 = __fmul_rn(k23.y, 2048.0f);
    float ky2 = __fmul_rn(k45.x, 2048.0f), kx2 = __fmul_rn(k45.y, 2048.0f);

    float ymin = fminf(fminf(ky0, ky1), ky2) - 2.5f;
    float ymax = fmaxf(fmaxf(ky0, ky1), ky2) + 2.5f;
    float xmin = fminf(fminf(kx0, kx1), kx2) - 2.5f;
    float xmax = fmaxf(fmaxf(kx0, kx1), kx2) + 2.5f;

    if ((float)(y0 + TILE_H - 1) < ymin || (float)y0 > ymax ||
        (float)(x0 + TILE_W - 1) < xmin || (float)x0 > xmax)
        return;                           // ~99% of warps exit here (~18 instrs)

    // ---- phase 3: per-lane sample (ref-matched rounding), exact box prune ----
    // t_i = i * fl(1/31), endpoint forced to 1.0 (matches jnp.linspace)
    float t = (tx == 31) ? 1.0f : (float)tx * (1.0f / 31.0f);
    float u = __fsub_rn(1.0f, t);
    float b0 = __fmul_rn(u, u);
    float b1 = __fmul_rn(__fmul_rn(2.0f, t), u);
    float b2 = __fmul_rn(t, t);
    float py = __fadd_rn(__fadd_rn(__fmul_rn(b0, ky0), __fmul_rn(b1, ky1)),
                         __fmul_rn(b2, ky2));
    float px = __fadd_rn(__fadd_rn(__fmul_rn(b0, kx0), __fmul_rn(b1, kx1)),
                         __fmul_rn(b2, kx2));

    // Exact point-to-tile-box distance; squared threshold 4.5 (> 4.0) pads for
    // rounding — only ever KEEPS extra samples (dist(pixel,s) >= boxdist(s)).
    float bdy = fmaxf(fmaxf((float)y0 - py, py - (float)(y0 + TILE_H - 1)), 0.0f);
    float bdx = fmaxf(fmaxf((float)x0 - px, px - (float)(x0 + TILE_W - 1)), 0.0f);
    bool near = (bdy * bdy + bdx * bdx) < 4.5f;
    unsigned mask = __ballot_sync(0xffffffffu, near);

    if (mask == 0u) return;

    // ---- phase 4 (rare): full min for this thread's 4 pixels, overwrite ----
    const float maxd = sqrtf(2048.0f * 2048.0f + 2048.0f * 2048.0f);
    const float fy  = (float)y;
    const float fx0 = (float)x;
    const float fx1 = fx0 + 1.0f;
    const float fx2 = fx0 + 2.0f;
    const float fx3 = fx0 + 3.0f;
    float m0 = 3.4e38f, m1 = 3.4e38f, m2 = 3.4e38f, m3 = 3.4e38f;
    unsigned mm = mask;                  // warp-uniform loop
    while (mm) {
        int lane = __ffs(mm) - 1;
        mm &= mm - 1u;
        float syv = __shfl_sync(0xffffffffu, py, lane);
        float sxv = __shfl_sync(0xffffffffu, px, lane);
        float dy  = __fsub_rn(fy, syv);
        float dy2 = __fmul_rn(dy, dy);   // separate op, matches reference
        float d;
        d = __fsub_rn(fx0, sxv); m0 = fminf(m0, __fadd_rn(dy2, __fmul_rn(d, d)));
        d = __fsub_rn(fx1, sxv); m1 = fminf(m1, __fadd_rn(dy2, __fmul_rn(d, d)));
        d = __fsub_rn(fx2, sxv); m2 = fminf(m2, __fadd_rn(dy2, __fmul_rn(d, d)));
        d = __fsub_rn(fx3, sxv); m3 = fminf(m3, __fadd_rn(dy2, __fmul_rn(d, d)));
    }
    // sqrt BEFORE compare (boundary rounding identical to reference)
    float d0 = sqrtf(m0), d1 = sqrtf(m1), d2s = sqrtf(m2), d3 = sqrtf(m3);
    float4 v;
    v.x = (d0  < 2.0f) ? __fsub_rn(1.0f, __fdiv_rn(d0,  maxd)) : 0.0f;
    v.y = (d1  < 2.0f) ? __fsub_rn(1.0f, __fdiv_rn(d1,  maxd)) : 0.0f;
    v.z = (d2s < 2.0f) ? __fsub_rn(1.0f, __fdiv_rn(d2s, maxd)) : 0.0f;
    v.w = (d3  < 2.0f) ? __fsub_rn(1.0f, __fdiv_rn(d3,  maxd)) : 0.0f;
    *reinterpret_cast<float4*>(base) = v;
}

extern "C" void kernel_launch(void* const* d_in, const int* in_sizes, int n_in,
                              void* d_out, int out_size)
{
    const float* kp = (const float*)d_in[0];   // [3,2] normalized (y,x)
    float* out = (float*)d_out;                // [2048,2048] fp32

    dim3 block(32, 8);
    dim3 grid(CANVAS_W / TILE_W, CANVAS_H / TILE_H);  // (16, 256) = 4096 blocks
    path_raster_kernel<<<grid, block>>>(kp, out);
}